// round 5
// baseline (speedup 1.0000x reference)
#include <cuda_runtime.h>
#include <math.h>

// Problem constants
#define B_    4
#define H_    8
#define E_    64
#define L_    2048
#define N_    2048           // FFT length
#define LF_   1025           // rfft bins
#define BH_   32             // B*H
#define CC_   128            // 2*E (interleaved re/im)

typedef unsigned long long u64;

// ---------------- device scratch (no allocations allowed) ----------------
__device__ float g_Qf[(size_t)BH_ * LF_ * CC_];   // [bh][x][2e+{0,1}]  ~16.8MB
__device__ float g_Kf[(size_t)BH_ * LF_ * CC_];
__device__ float g_Vf[(size_t)BH_ * LF_ * CC_];
__device__ float g_Of[(size_t)BH_ * LF_ * CC_];
__device__ float g_P [(size_t)BH_ * LF_ * LF_];   // scores -> probs, ~134.5MB
__device__ float g_twr[1024];
__device__ float g_twi[1024];

// 1/sqrt(2048)
#define ORTHO_SCALE 0.02209708691207961f

// packed f32x2 FMA: acc = a*b + acc (per 32-bit lane, rn) — sm_100+ FFMA2 path
#define FMA2(acc, a, b) \
    asm("fma.rn.f32x2 %0, %1, %2, %0;" : "+l"(acc) : "l"(a), "l"(b))

__device__ __forceinline__ u64 pack2(float lo, float hi) {
    return ((u64)__float_as_uint(hi) << 32) | (u64)__float_as_uint(lo);
}
__device__ __forceinline__ u64 dup2(float v) {
    unsigned u = __float_as_uint(v);
    return ((u64)u << 32) | (u64)u;
}
__device__ __forceinline__ float lo32(u64 v) { return __uint_as_float((unsigned)v); }
__device__ __forceinline__ float hi32(u64 v) { return __uint_as_float((unsigned)(v >> 32)); }

// ---------------- twiddle init ----------------
__global__ void init_tw_kernel() {
    int k = blockIdx.x * blockDim.x + threadIdx.x;
    if (k < 1024) {
        float s, c;
        sincospif(-(float)k / 1024.0f, &s, &c);
        g_twr[k] = c;
        g_twi[k] = s;
    }
}

// ---------------- shared-memory radix-2 DIT core (N=2048, 256 threads) ----
__device__ __forceinline__ void fft_core(float* sr, float* si, bool inverse) {
    #pragma unroll 1
    for (int s = 1; s <= 11; s++) {
        int half  = 1 << (s - 1);
        int shift = 11 - s;
        for (int j = threadIdx.x; j < 1024; j += 256) {
            int pos = j & (half - 1);
            int i1  = ((j >> (s - 1)) << s) + pos;
            int i2  = i1 + half;
            int ti  = pos << shift;
            float wr = g_twr[ti];
            float wi = inverse ? -g_twi[ti] : g_twi[ti];
            float xr = sr[i2], xi = si[i2];
            float tr = wr * xr - wi * xi;
            float tq = wr * xi + wi * xr;
            float ar = sr[i1], ai = si[i1];
            sr[i2] = ar - tr;  si[i2] = ai - tq;
            sr[i1] = ar + tr;  si[i1] = ai + tq;
        }
        __syncthreads();
    }
}

// ---------------- forward rfft for q/k/v ----------------
__global__ void fft_fwd_kernel(const float* __restrict__ q,
                               const float* __restrict__ k,
                               const float* __restrict__ v) {
    __shared__ float sr[2048];
    __shared__ float si[2048];
    int bhe = blockIdx.x;
    int t   = blockIdx.y;
    int b = bhe >> 9;
    int h = (bhe >> 6) & 7;
    int e = bhe & 63;
    const float* src = (t == 0) ? q : ((t == 1) ? k : v);
    const float* base = src + (size_t)b * L_ * (H_ * E_) + h * E_ + e;

    for (int l = threadIdx.x; l < 2048; l += 256) {
        int r = __brev((unsigned)l) >> 21;
        sr[r] = base[(size_t)l * (H_ * E_)];
        si[r] = 0.0f;
    }
    __syncthreads();
    fft_core(sr, si, false);

    float* dst = (t == 0) ? g_Qf : ((t == 1) ? g_Kf : g_Vf);
    int bh = b * H_ + h;
    float* o = dst + (size_t)bh * LF_ * CC_;
    for (int x = threadIdx.x; x < LF_; x += 256) {
        o[(size_t)x * CC_ + 2 * e]     = sr[x] * ORTHO_SCALE;
        o[(size_t)x * CC_ + 2 * e + 1] = si[x] * ORTHO_SCALE;
    }
}

// ---------------- scores: |Q^H conj(K)|/sqrt(E) via packed FFMA2 ----------
// tile 64x64, 256 threads (16x16), 4x4 micro-tile.
// SMEM planes (u64, row stride 65):
//   Qp0[x][e] = (qr, qi)       Qp1[x][e] = (qi, -qr)
//   Krd[y][e] = (kr, kr)       Kid[y][e] = (ki, ki)
// acc[i][j] (u64) accumulates (re, im):
//   (qr,qi)*(kr,kr) = (qr*kr, qi*kr);  (qi,-qr)*(ki,ki) = (qi*ki, -qr*ki)
#define SCPADU 65
#define SCORES_SMEM (4 * 64 * SCPADU * 8)

__global__ void __launch_bounds__(256) scores_kernel() {
    extern __shared__ u64 sh[];
    u64* Qp0 = sh;
    u64* Qp1 = Qp0 + 64 * SCPADU;
    u64* Krd = Qp1 + 64 * SCPADU;
    u64* Kid = Krd + 64 * SCPADU;

    int tid = threadIdx.x;
    int bh = blockIdx.z;
    int x0 = blockIdx.x * 64;
    int y0 = blockIdx.y * 64;

    const float* Qg = g_Qf + (size_t)bh * LF_ * CC_;
    const float* Kg = g_Kf + (size_t)bh * LF_ * CC_;

    for (int idx = tid; idx < 64 * 32; idx += 256) {
        int r  = idx >> 5;
        int c4 = idx & 31;    // float4 index -> e-pairs 2c4, 2c4+1
        float4 vq = make_float4(0.f, 0.f, 0.f, 0.f);
        float4 vk = make_float4(0.f, 0.f, 0.f, 0.f);
        if (x0 + r < LF_) vq = *(const float4*)(Qg + (size_t)(x0 + r) * CC_ + c4 * 4);
        if (y0 + r < LF_) vk = *(const float4*)(Kg + (size_t)(y0 + r) * CC_ + c4 * 4);
        int bq = r * SCPADU + 2 * c4;
        Qp0[bq]     = pack2(vq.x, vq.y);
        Qp0[bq + 1] = pack2(vq.z, vq.w);
        Qp1[bq]     = pack2(vq.y, -vq.x);
        Qp1[bq + 1] = pack2(vq.w, -vq.z);
        Krd[bq]     = dup2(vk.x);
        Krd[bq + 1] = dup2(vk.z);
        Kid[bq]     = dup2(vk.y);
        Kid[bq + 1] = dup2(vk.w);
    }
    __syncthreads();

    int tx = tid & 15;
    int ty = tid >> 4;

    u64 acc[4][4];
    #pragma unroll
    for (int i = 0; i < 4; i++)
        #pragma unroll
        for (int j = 0; j < 4; j++) acc[i][j] = 0ULL;

    #pragma unroll 2
    for (int e = 0; e < 64; e++) {
        u64 qv[4], qw[4], kr[4], ki[4];
        #pragma unroll
        for (int i = 0; i < 4; i++) {
            qv[i] = Qp0[(ty + 16 * i) * SCPADU + e];
            qw[i] = Qp1[(ty + 16 * i) * SCPADU + e];
        }
        #pragma unroll
        for (int j = 0; j < 4; j++) {
            kr[j] = Krd[(tx + 16 * j) * SCPADU + e];
            ki[j] = Kid[(tx + 16 * j) * SCPADU + e];
        }
        #pragma unroll
        for (int i = 0; i < 4; i++)
            #pragma unroll
            for (int j = 0; j < 4; j++) {
                FMA2(acc[i][j], qv[i], kr[j]);
                FMA2(acc[i][j], qw[i], ki[j]);
            }
    }

    float* Pg = g_P + (size_t)bh * LF_ * LF_;
    #pragma unroll
    for (int i = 0; i < 4; i++) {
        int x = x0 + ty + 16 * i;
        if (x >= LF_) continue;
        #pragma unroll
        for (int j = 0; j < 4; j++) {
            int y = y0 + tx + 16 * j;
            if (y >= LF_) continue;
            float re = lo32(acc[i][j]);
            float im = hi32(acc[i][j]);
            Pg[(size_t)x * LF_ + y] = sqrtf(re * re + im * im) * 0.125f;
        }
    }
}

// ---------------- row softmax over y (1025), register-resident ------------
// grid (1025, 32), 256 threads
__global__ void __launch_bounds__(256) softmax_kernel() {
    __shared__ float red[8];
    int tid = threadIdx.x;
    float* row = g_P + ((size_t)blockIdx.y * LF_ + blockIdx.x) * LF_;

    float v[5];
    #pragma unroll
    for (int k = 0; k < 4; k++) v[k] = row[tid + 256 * k];
    v[4] = (tid == 0) ? row[1024] : -3.4e38f;

    float m = fmaxf(fmaxf(fmaxf(v[0], v[1]), fmaxf(v[2], v[3])), v[4]);
    #pragma unroll
    for (int o = 16; o > 0; o >>= 1) m = fmaxf(m, __shfl_xor_sync(0xffffffffu, m, o));
    if ((tid & 31) == 0) red[tid >> 5] = m;
    __syncthreads();
    float mx = red[0];
    #pragma unroll
    for (int w = 1; w < 8; w++) mx = fmaxf(mx, red[w]);
    __syncthreads();

    float s = 0.f;
    #pragma unroll
    for (int k = 0; k < 4; k++) { v[k] = __expf(v[k] - mx); s += v[k]; }
    v[4] = (tid == 0) ? __expf(v[4] - mx) : 0.f;
    s += v[4];
    #pragma unroll
    for (int o = 16; o > 0; o >>= 1) s += __shfl_xor_sync(0xffffffffu, s, o);
    if ((tid & 31) == 0) red[tid >> 5] = s;
    __syncthreads();
    float tot = 0.f;
    #pragma unroll
    for (int w = 0; w < 8; w++) tot += red[w];
    float inv = 1.0f / tot;

    #pragma unroll
    for (int k = 0; k < 4; k++) row[tid + 256 * k] = v[k] * inv;
    if (tid == 0) row[1024] = v[4] * inv;
}

// ---------------- output mix: Of[x][c] = sum_y P[x][y]*Vf[y][c] (FFMA2) ---
// block: 64 x-rows, full 128 c, y chunked by 64. 256 threads:
//   ct = tid&31 -> c-pairs ct, ct+32;  rg = tid>>5 -> rows rg*8..rg*8+7
// SMEM: Pd[x][y] = (p,p) dup u64;  Vs[y][cp] = (v_even, v_odd) u64
#define OGPAD 65
#define OUTG_SMEM (2 * 64 * OGPAD * 8)

__global__ void __launch_bounds__(256) outgemm_kernel() {
    extern __shared__ u64 sh2[];
    u64* Pd = sh2;
    u64* Vs = Pd + 64 * OGPAD;

    int tid = threadIdx.x;
    int ct = tid & 31;
    int rg = tid >> 5;
    int bh = blockIdx.y;
    int x0 = blockIdx.x * 64;

    const float* Pg = g_P + (size_t)bh * LF_ * LF_;
    const float* Vg = g_Vf + (size_t)bh * LF_ * CC_;

    u64 acc[8][2];
    #pragma unroll
    for (int r = 0; r < 8; r++) { acc[r][0] = 0ULL; acc[r][1] = 0ULL; }

    for (int yt = 0; yt < 17; yt++) {
        int y0 = yt * 64;
        for (int idx = tid; idx < 64 * 64; idx += 256) {
            int r = idx >> 6, c = idx & 63;
            int xx = x0 + r, yy = y0 + c;
            float p = (xx < LF_ && yy < LF_) ? Pg[(size_t)xx * LF_ + yy] : 0.f;
            Pd[r * OGPAD + c] = dup2(p);
        }
        for (int idx = tid; idx < 64 * 32; idx += 256) {
            int r = idx >> 5, c4 = idx & 31;
            float4 v = make_float4(0.f, 0.f, 0.f, 0.f);
            if (y0 + r < LF_) v = *(const float4*)(Vg + (size_t)(y0 + r) * CC_ + c4 * 4);
            Vs[r * OGPAD + 2 * c4]     = pack2(v.x, v.y);
            Vs[r * OGPAD + 2 * c4 + 1] = pack2(v.z, v.w);
        }
        __syncthreads();

        #pragma unroll 4
        for (int y = 0; y < 64; y++) {
            u64 v0 = Vs[y * OGPAD + ct];
            u64 v1 = Vs[y * OGPAD + ct + 32];
            #pragma unroll
            for (int r = 0; r < 8; r++) {
                u64 p = Pd[(rg * 8 + r) * OGPAD + y];
                FMA2(acc[r][0], p, v0);
                FMA2(acc[r][1], p, v1);
            }
        }
        __syncthreads();
    }

    float* Og = g_Of + (size_t)bh * LF_ * CC_;
    #pragma unroll
    for (int r = 0; r < 8; r++) {
        int x = x0 + rg * 8 + r;
        if (x < LF_) {
            *(u64*)(Og + (size_t)x * CC_ + 2 * ct)        = acc[r][0];
            *(u64*)(Og + (size_t)x * CC_ + 2 * (ct + 32)) = acc[r][1];
        }
    }
}

// ---------------- inverse: Hermitian extend + inverse FFT, real part ------
__global__ void fft_inv_kernel(float* __restrict__ out) {
    __shared__ float sr[2048];
    __shared__ float si[2048];
    __shared__ float xr[LF_];
    __shared__ float xi[LF_];

    int bhe = blockIdx.x;
    int b = bhe >> 9;
    int h = (bhe >> 6) & 7;
    int e = bhe & 63;
    int bh = b * H_ + h;

    const float* src = g_Of + (size_t)bh * LF_ * CC_ + 2 * e;
    for (int x = threadIdx.x; x < LF_; x += 256) {
        xr[x] = src[(size_t)x * CC_];
        xi[x] = src[(size_t)x * CC_ + 1];
    }
    __syncthreads();

    for (int k = threadIdx.x; k < 2048; k += 256) {
        float vr, vi;
        if (k <= 1024) { vr = xr[k];        vi = xi[k]; }
        else           { vr = xr[2048 - k]; vi = -xi[2048 - k]; }
        int r = __brev((unsigned)k) >> 21;
        sr[r] = vr;
        si[r] = vi;
    }
    __syncthreads();
    fft_core(sr, si, true);

    float* o = out + (size_t)b * L_ * (H_ * E_) + h * E_ + e;
    for (int l = threadIdx.x; l < 2048; l += 256)
        o[(size_t)l * (H_ * E_)] = sr[l] * ORTHO_SCALE;
}

// ---------------- launch ----------------
extern "C" void kernel_launch(void* const* d_in, const int* in_sizes, int n_in,
                              void* d_out, int out_size) {
    (void)in_sizes; (void)n_in; (void)out_size;
    const float* q = (const float*)d_in[0];
    const float* k = (const float*)d_in[1];
    const float* v = (const float*)d_in[2];
    float* out = (float*)d_out;

    cudaFuncSetAttribute(scores_kernel,
                         cudaFuncAttributeMaxDynamicSharedMemorySize,
                         SCORES_SMEM);
    cudaFuncSetAttribute(outgemm_kernel,
                         cudaFuncAttributeMaxDynamicSharedMemorySize,
                         OUTG_SMEM);

    init_tw_kernel<<<4, 256>>>();
    fft_fwd_kernel<<<dim3(B_ * H_ * E_, 3), 256>>>(q, k, v);
    scores_kernel<<<dim3(17, 17, BH_), 256, SCORES_SMEM>>>();
    softmax_kernel<<<dim3(LF_, BH_), 256>>>();
    outgemm_kernel<<<dim3(17, BH_), 256, OUTG_SMEM>>>();
    fft_inv_kernel<<<B_ * H_ * E_, 256>>>(out);
}

// round 8
// speedup vs baseline: 1.6715x; 1.6715x over previous
#include <cuda_runtime.h>
#include <math.h>
#include <stdint.h>

// ---------------- problem constants ----------------
#define B_    4
#define H_    8
#define E_    64
#define L_    2048
#define LF_   1025
#define BH_   32
#define CC_   128            // 2*E floats per frequency bin
#define XP_   1152           // padded rows: 9*128
#define KP_   1088           // padded K for outgemm: 34*32

#define ORTHO_SCALE 0.02209708691207961f   // 1/sqrt(2048)

// ---------------- device scratch (zero-initialized .bss; padding stays 0) --
__device__ float g_Qp [(size_t)BH_ * XP_ * CC_];  // [bh][x][qr(0..63)|qi(64..127)] tf32
__device__ float g_Kp [(size_t)BH_ * XP_ * CC_];  // [bh][y][kr | ki]               tf32
__device__ float g_VfT[(size_t)BH_ * CC_ * KP_];  // [bh][c][y]                     tf32
__device__ float g_P  [(size_t)BH_ * XP_ * KP_];  // scores -> probs (padding = 0)
__device__ float g_Of [(size_t)BH_ * LF_ * CC_];  // mixed complex spectrum (f32)
__device__ float g_twr[1024];
__device__ float g_twi[1024];

// ---------------- helpers ----------------
static __device__ __forceinline__ float tf32r(float x) {
    uint32_t u;
    asm("cvt.rna.tf32.f32 %0, %1;" : "=r"(u) : "f"(x));
    return __uint_as_float(u);
}

// portable warp-level tf32 MMA (sm_80+; compiles for compute_103 target)
static __device__ __forceinline__ void mma8(float* d, const uint32_t* a, const uint32_t* b) {
    asm volatile(
        "mma.sync.aligned.m16n8k8.row.col.f32.tf32.tf32.f32 "
        "{%0,%1,%2,%3}, {%4,%5,%6,%7}, {%8,%9}, {%0,%1,%2,%3};"
        : "+f"(d[0]), "+f"(d[1]), "+f"(d[2]), "+f"(d[3])
        : "r"(a[0]), "r"(a[1]), "r"(a[2]), "r"(a[3]), "r"(b[0]), "r"(b[1]));
}

// ---------------- twiddle init ----------------
__global__ void init_tw_kernel() {
    int k = blockIdx.x * blockDim.x + threadIdx.x;
    if (k < 1024) {
        float s, c;
        sincospif(-(float)k / 1024.0f, &s, &c);
        g_twr[k] = c;
        g_twi[k] = s;
    }
}

// ---------------- shared-memory radix-2 DIT core (N=2048, 256 threads) ----
__device__ __forceinline__ void fft_core(float* sr, float* si, bool inverse) {
    #pragma unroll 1
    for (int s = 1; s <= 11; s++) {
        int half  = 1 << (s - 1);
        int shift = 11 - s;
        for (int j = threadIdx.x; j < 1024; j += 256) {
            int pos = j & (half - 1);
            int i1  = ((j >> (s - 1)) << s) + pos;
            int i2  = i1 + half;
            int ti  = pos << shift;
            float wr = g_twr[ti];
            float wi = inverse ? -g_twi[ti] : g_twi[ti];
            float xr = sr[i2], xi = si[i2];
            float tr = wr * xr - wi * xi;
            float tq = wr * xi + wi * xr;
            float ar = sr[i1], ai = si[i1];
            sr[i2] = ar - tr;  si[i2] = ai - tq;
            sr[i1] = ar + tr;  si[i1] = ai + tq;
        }
        __syncthreads();
    }
}

// ---------------- forward rfft q/k/v -> tf32 planar layouts ----------------
__global__ void fft_fwd_kernel(const float* __restrict__ q,
                               const float* __restrict__ k,
                               const float* __restrict__ v) {
    __shared__ float sr[2048];
    __shared__ float si[2048];
    int bhe = blockIdx.x;
    int t   = blockIdx.y;
    int b = bhe >> 9;
    int h = (bhe >> 6) & 7;
    int e = bhe & 63;
    int bh = b * H_ + h;
    const float* src = (t == 0) ? q : ((t == 1) ? k : v);
    const float* base = src + (size_t)b * L_ * (H_ * E_) + h * E_ + e;

    for (int l = threadIdx.x; l < 2048; l += 256) {
        int r = __brev((unsigned)l) >> 21;
        sr[r] = base[(size_t)l * (H_ * E_)];
        si[r] = 0.0f;
    }
    __syncthreads();
    fft_core(sr, si, false);

    if (t == 2) {
        float* vt = g_VfT + (size_t)bh * CC_ * KP_;
        for (int x = threadIdx.x; x < LF_; x += 256) {
            vt[(size_t)(2 * e)     * KP_ + x] = tf32r(sr[x] * ORTHO_SCALE);
            vt[(size_t)(2 * e + 1) * KP_ + x] = tf32r(si[x] * ORTHO_SCALE);
        }
    } else {
        float* dst = (t == 0) ? g_Qp : g_Kp;
        float* p = dst + (size_t)bh * XP_ * CC_;
        for (int x = threadIdx.x; x < LF_; x += 256) {
            p[(size_t)x * CC_ + e]      = tf32r(sr[x] * ORTHO_SCALE);
            p[(size_t)x * CC_ + 64 + e] = tf32r(si[x] * ORTHO_SCALE);
        }
    }
}

// ---------------- scores: mma.sync tf32, CTA tile 128x128, K=128 ----------
// SMEM: As[128][132] (Q planar), Bs[128][132] (K planar). 8 warps: wm=wid&3,
// wn=wid>>2; warp tile 32(m) x 64(n). Complex via planar halves:
//   re += Alo*Blo + Ahi*Bhi ;  im += Ahi*Blo + (-Alo)*Bhi
#define SC_STR  132
#define SC_SMEM (2 * 128 * SC_STR * 4)

__global__ void __launch_bounds__(256) scores_kernel() {
    extern __shared__ float sm[];
    float* As = sm;
    float* Bs = sm + 128 * SC_STR;

    int tid  = threadIdx.x;
    int wid  = tid >> 5;
    int lane = tid & 31;
    int g = lane >> 2;
    int t = lane & 3;
    int wm = wid & 3;
    int wn = wid >> 2;
    int bh = blockIdx.z;
    int x0 = blockIdx.x * 128;
    int y0 = blockIdx.y * 128;

    const float* Qg = g_Qp + (size_t)bh * XP_ * CC_;
    const float* Kg = g_Kp + (size_t)bh * XP_ * CC_;

    for (int idx = tid; idx < 4096; idx += 256) {
        int r  = idx >> 5;
        int f4 = idx & 31;
        *(float4*)&As[r * SC_STR + f4 * 4] = *(const float4*)(Qg + (size_t)(x0 + r) * CC_ + f4 * 4);
        *(float4*)&Bs[r * SC_STR + f4 * 4] = *(const float4*)(Kg + (size_t)(y0 + r) * CC_ + f4 * 4);
    }
    __syncthreads();

    float accr[2][8][4];
    float acci[2][8][4];
    #pragma unroll
    for (int mf = 0; mf < 2; mf++)
        #pragma unroll
        for (int nf = 0; nf < 8; nf++)
            #pragma unroll
            for (int j = 0; j < 4; j++) { accr[mf][nf][j] = 0.f; acci[mf][nf][j] = 0.f; }

    #pragma unroll 1
    for (int kc = 0; kc < 8; kc++) {
        int c0 = kc * 8 + t;
        uint32_t alo[2][4], ahi[2][4], aln[2][4];
        #pragma unroll
        for (int mf = 0; mf < 2; mf++) {
            int r0 = (wm * 32 + mf * 16 + g) * SC_STR;
            int r1 = r0 + 8 * SC_STR;
            alo[mf][0] = __float_as_uint(As[r0 + c0]);
            alo[mf][1] = __float_as_uint(As[r1 + c0]);
            alo[mf][2] = __float_as_uint(As[r0 + c0 + 4]);
            alo[mf][3] = __float_as_uint(As[r1 + c0 + 4]);
            ahi[mf][0] = __float_as_uint(As[r0 + c0 + 64]);
            ahi[mf][1] = __float_as_uint(As[r1 + c0 + 64]);
            ahi[mf][2] = __float_as_uint(As[r0 + c0 + 68]);
            ahi[mf][3] = __float_as_uint(As[r1 + c0 + 68]);
            #pragma unroll
            for (int j = 0; j < 4; j++) aln[mf][j] = alo[mf][j] ^ 0x80000000u;
        }
        #pragma unroll
        for (int nf = 0; nf < 8; nf++) {
            int rB = (wn * 64 + nf * 8 + g) * SC_STR;
            uint32_t blo[2], bhi[2];
            blo[0] = __float_as_uint(Bs[rB + c0]);
            blo[1] = __float_as_uint(Bs[rB + c0 + 4]);
            bhi[0] = __float_as_uint(Bs[rB + c0 + 64]);
            bhi[1] = __float_as_uint(Bs[rB + c0 + 68]);
            #pragma unroll
            for (int mf = 0; mf < 2; mf++) {
                mma8(accr[mf][nf], alo[mf], blo);
                mma8(accr[mf][nf], ahi[mf], bhi);
                mma8(acci[mf][nf], ahi[mf], blo);
                mma8(acci[mf][nf], aln[mf], bhi);
            }
        }
    }

    float* Pg = g_P + (size_t)bh * XP_ * KP_;
    #pragma unroll
    for (int mf = 0; mf < 2; mf++)
        #pragma unroll
        for (int nf = 0; nf < 8; nf++)
            #pragma unroll
            for (int j = 0; j < 4; j++) {
                int x = x0 + wm * 32 + mf * 16 + g + ((j >= 2) ? 8 : 0);
                int y = y0 + wn * 64 + nf * 8 + t * 2 + (j & 1);
                if (x < LF_ && y < LF_) {
                    float re = accr[mf][nf][j];
                    float im = acci[mf][nf][j];
                    Pg[(size_t)x * KP_ + y] = sqrtf(re * re + im * im) * 0.125f;
                }
            }
}

// ---------------- row softmax over y (1025), register-resident ------------
__global__ void __launch_bounds__(256) softmax_kernel() {
    __shared__ float red[8];
    int tid = threadIdx.x;
    float* row = g_P + ((size_t)blockIdx.y * XP_ + blockIdx.x) * KP_;

    float v[5];
    #pragma unroll
    for (int k = 0; k < 4; k++) v[k] = row[tid + 256 * k];
    v[4] = (tid == 0) ? row[1024] : -3.4e38f;

    float m = fmaxf(fmaxf(fmaxf(v[0], v[1]), fmaxf(v[2], v[3])), v[4]);
    #pragma unroll
    for (int o = 16; o > 0; o >>= 1) m = fmaxf(m, __shfl_xor_sync(0xffffffffu, m, o));
    if ((tid & 31) == 0) red[tid >> 5] = m;
    __syncthreads();
    float mx = red[0];
    #pragma unroll
    for (int w = 1; w < 8; w++) mx = fmaxf(mx, red[w]);
    __syncthreads();

    float s = 0.f;
    #pragma unroll
    for (int k = 0; k < 4; k++) { v[k] = __expf(v[k] - mx); s += v[k]; }
    v[4] = (tid == 0) ? __expf(v[4] - mx) : 0.f;
    s += v[4];
    #pragma unroll
    for (int o = 16; o > 0; o >>= 1) s += __shfl_xor_sync(0xffffffffu, s, o);
    if ((tid & 31) == 0) red[tid >> 5] = s;
    __syncthreads();
    float tot = 0.f;
    #pragma unroll
    for (int w = 0; w < 8; w++) tot += red[w];
    float inv = 1.0f / tot;

    #pragma unroll
    for (int k = 0; k < 4; k++) row[tid + 256 * k] = tf32r(v[k] * inv);
    if (tid == 0) row[1024] = tf32r(v[4] * inv);
}

// ---------------- outgemm: D[x][c] = sum_y P[x][y]*VfT[c][y] (mma.sync) ---
// CTA tile 128(x) x 128(c), K=1088 in 17 chunks of 64. Same warp layout.
#define OG_STR  68
#define OG_SMEM (2 * 128 * OG_STR * 4)

__global__ void __launch_bounds__(256) outgemm_kernel() {
    extern __shared__ float sm[];
    float* As = sm;
    float* Bs = sm + 128 * OG_STR;

    int tid  = threadIdx.x;
    int wid  = tid >> 5;
    int lane = tid & 31;
    int g = lane >> 2;
    int t = lane & 3;
    int wm = wid & 3;
    int wn = wid >> 2;
    int bh = blockIdx.y;
    int x0 = blockIdx.x * 128;

    const float* Pg = g_P   + (size_t)bh * XP_ * KP_;
    const float* Vt = g_VfT + (size_t)bh * CC_ * KP_;

    float acc[2][8][4];
    #pragma unroll
    for (int mf = 0; mf < 2; mf++)
        #pragma unroll
        for (int nf = 0; nf < 8; nf++)
            #pragma unroll
            for (int j = 0; j < 4; j++) acc[mf][nf][j] = 0.f;

    #pragma unroll 1
    for (int ych = 0; ych < 17; ych++) {
        int y0 = ych * 64;
        for (int idx = tid; idx < 2048; idx += 256) {
            int r = idx >> 4, f4 = idx & 15;
            *(float4*)&As[r * OG_STR + f4 * 4] = *(const float4*)(Pg + (size_t)(x0 + r) * KP_ + y0 + f4 * 4);
            *(float4*)&Bs[r * OG_STR + f4 * 4] = *(const float4*)(Vt + (size_t)r * KP_ + y0 + f4 * 4);
        }
        __syncthreads();

        #pragma unroll
        for (int kc = 0; kc < 8; kc++) {
            int c0 = kc * 8 + t;
            uint32_t af[2][4];
            #pragma unroll
            for (int mf = 0; mf < 2; mf++) {
                int r0 = (wm * 32 + mf * 16 + g) * OG_STR;
                int r1 = r0 + 8 * OG_STR;
                af[mf][0] = __float_as_uint(As[r0 + c0]);
                af[mf][1] = __float_as_uint(As[r1 + c0]);
                af[mf][2] = __float_as_uint(As[r0 + c0 + 4]);
                af[mf][3] = __float_as_uint(As[r1 + c0 + 4]);
            }
            #pragma unroll
            for (int nf = 0; nf < 8; nf++) {
                int rB = (wn * 64 + nf * 8 + g) * OG_STR;
                uint32_t bf[2];
                bf[0] = __float_as_uint(Bs[rB + c0]);
                bf[1] = __float_as_uint(Bs[rB + c0 + 4]);
                #pragma unroll
                for (int mf = 0; mf < 2; mf++)
                    mma8(acc[mf][nf], af[mf], bf);
            }
        }
        __syncthreads();
    }

    float* Og = g_Of + (size_t)bh * LF_ * CC_;
    #pragma unroll
    for (int mf = 0; mf < 2; mf++)
        #pragma unroll
        for (int nf = 0; nf < 8; nf++)
            #pragma unroll
            for (int j = 0; j < 4; j++) {
                int x = x0 + wm * 32 + mf * 16 + g + ((j >= 2) ? 8 : 0);
                int c = wn * 64 + nf * 8 + t * 2 + (j & 1);
                if (x < LF_)
                    Og[(size_t)x * CC_ + c] = acc[mf][nf][j];
            }
}

// ---------------- inverse: Hermitian extend + inverse FFT, real part ------
__global__ void fft_inv_kernel(float* __restrict__ out) {
    __shared__ float sr[2048];
    __shared__ float si[2048];
    __shared__ float xr[LF_];
    __shared__ float xi[LF_];

    int bhe = blockIdx.x;
    int b = bhe >> 9;
    int h = (bhe >> 6) & 7;
    int e = bhe & 63;
    int bh = b * H_ + h;

    const float* src = g_Of + (size_t)bh * LF_ * CC_ + 2 * e;
    for (int x = threadIdx.x; x < LF_; x += 256) {
        xr[x] = src[(size_t)x * CC_];
        xi[x] = src[(size_t)x * CC_ + 1];
    }
    __syncthreads();

    for (int k = threadIdx.x; k < 2048; k += 256) {
        float vr, vi;
        if (k <= 1024) { vr = xr[k];        vi = xi[k]; }
        else           { vr = xr[2048 - k]; vi = -xi[2048 - k]; }
        int r = __brev((unsigned)k) >> 21;
        sr[r] = vr;
        si[r] = vi;
    }
    __syncthreads();
    fft_core(sr, si, true);

    float* o = out + (size_t)b * L_ * (H_ * E_) + h * E_ + e;
    for (int l = threadIdx.x; l < 2048; l += 256)
        o[(size_t)l * (H_ * E_)] = sr[l] * ORTHO_SCALE;
}

// ---------------- launch ----------------
extern "C" void kernel_launch(void* const* d_in, const int* in_sizes, int n_in,
                              void* d_out, int out_size) {
    (void)in_sizes; (void)n_in; (void)out_size;
    const float* q = (const float*)d_in[0];
    const float* k = (const float*)d_in[1];
    const float* v = (const float*)d_in[2];
    float* out = (float*)d_out;

    cudaFuncSetAttribute(scores_kernel,
                         cudaFuncAttributeMaxDynamicSharedMemorySize, SC_SMEM);
    cudaFuncSetAttribute(outgemm_kernel,
                         cudaFuncAttributeMaxDynamicSharedMemorySize, OG_SMEM);

    init_tw_kernel<<<4, 256>>>();
    fft_fwd_kernel<<<dim3(B_ * H_ * E_, 3), 256>>>(q, k, v);
    scores_kernel<<<dim3(9, 9, BH_), 256, SC_SMEM>>>();
    softmax_kernel<<<dim3(LF_, BH_), 256>>>();
    outgemm_kernel<<<dim3(9, BH_), 256, OG_SMEM>>>();
    fft_inv_kernel<<<B_ * H_ * E_, 256>>>(out);
}

// round 9
// speedup vs baseline: 2.5635x; 1.5336x over previous
#include <cuda_runtime.h>
#include <math.h>
#include <stdint.h>

// ---------------- problem constants ----------------
#define B_    4
#define H_    8
#define E_    64
#define L_    2048
#define LF_   1025
#define BH_   32
#define CC_   128            // 2*E floats per frequency bin
#define XP_   1152           // padded rows: 9*128
#define KP_   1088           // padded K for outgemm: 34*32

#define ORTHO_SCALE 0.02209708691207961f   // 1/sqrt(2048)

// ---------------- device scratch (zero-initialized .bss; padding stays 0) --
__device__ float g_Qp [(size_t)BH_ * XP_ * CC_];  // [bh][x][qr(0..63)|qi(64..127)] tf32
__device__ float g_Kp [(size_t)BH_ * XP_ * CC_];  // [bh][y][kr | ki]               tf32
__device__ float g_VfT[(size_t)BH_ * CC_ * KP_];  // [bh][c][y]                     tf32
__device__ float g_P  [(size_t)BH_ * XP_ * KP_];  // scores -> probs (padding = 0)
__device__ float g_Of [(size_t)BH_ * LF_ * CC_];  // mixed complex spectrum (f32)
__device__ float g_twr[1024];
__device__ float g_twi[1024];

// ---------------- helpers ----------------
static __device__ __forceinline__ float tf32r(float x) {
    uint32_t u;
    asm("cvt.rna.tf32.f32 %0, %1;" : "=r"(u) : "f"(x));
    return __uint_as_float(u);
}

// portable warp-level tf32 MMA (sm_80+; compiles for compute_103 target)
static __device__ __forceinline__ void mma8(float* d, const uint32_t* a, const uint32_t* b) {
    asm volatile(
        "mma.sync.aligned.m16n8k8.row.col.f32.tf32.tf32.f32 "
        "{%0,%1,%2,%3}, {%4,%5,%6,%7}, {%8,%9}, {%0,%1,%2,%3};"
        : "+f"(d[0]), "+f"(d[1]), "+f"(d[2]), "+f"(d[3])
        : "r"(a[0]), "r"(a[1]), "r"(a[2]), "r"(a[3]), "r"(b[0]), "r"(b[1]));
}

// ---------------- twiddle init ----------------
__global__ void init_tw_kernel() {
    int k = blockIdx.x * blockDim.x + threadIdx.x;
    if (k < 1024) {
        float s, c;
        sincospif(-(float)k / 1024.0f, &s, &c);
        g_twr[k] = c;
        g_twi[k] = s;
    }
}

// ------- batched shared-memory radix-2 DIT core: 4 FFTs of N=2048 ---------
// layout: fft f occupies sm[f*4096 .. f*4096+2047] (re), +2048 (im)
__device__ __forceinline__ void fft_core4(float* sm_, bool inverse, int nthr) {
    #pragma unroll 1
    for (int s = 1; s <= 11; s++) {
        int half  = 1 << (s - 1);
        int shift = 11 - s;
        for (int jj = threadIdx.x; jj < 4096; jj += nthr) {
            int f = jj >> 10;
            int j = jj & 1023;
            float* sr = sm_ + f * 4096;
            float* si = sr + 2048;
            int pos = j & (half - 1);
            int i1  = ((j >> (s - 1)) << s) + pos;
            int i2  = i1 + half;
            int ti  = pos << shift;
            float wr = g_twr[ti];
            float wi = inverse ? -g_twi[ti] : g_twi[ti];
            float xr = sr[i2], xi = si[i2];
            float tr = wr * xr - wi * xi;
            float tq = wr * xi + wi * xr;
            float ar = sr[i1], ai = si[i1];
            sr[i2] = ar - tr;  si[i2] = ai - tq;
            sr[i1] = ar + tr;  si[i1] = ai + tq;
        }
        __syncthreads();
    }
}

// ---------------- forward rfft, 8 channels per block (real-pair packing) ---
// grid (BH, 8 e-groups, 3 tensors), 512 threads, 64KB dynamic smem.
// z_j = x_{2j} + i x_{2j+1};  F = (Z(k)+conj(Z(N-k)))/2,  G = -i(Z(k)-conj(Z(N-k)))/2
#define FFT_SMEM (4 * 4096 * 4)

__global__ void __launch_bounds__(512) fft_fwd_kernel(const float* __restrict__ q,
                                                      const float* __restrict__ k,
                                                      const float* __restrict__ v) {
    extern __shared__ float sm_[];
    int bh = blockIdx.x;
    int eg = blockIdx.y;
    int t  = blockIdx.z;
    int b = bh >> 3;
    int h = bh & 7;
    const float* src = (t == 0) ? q : ((t == 1) ? k : v);
    const float* base = src + (size_t)b * L_ * (H_ * E_) + h * E_ + eg * 8;

    for (int l = threadIdx.x; l < 2048; l += 512) {
        const float* p = base + (size_t)l * (H_ * E_);
        float4 a0 = *(const float4*)(p);
        float4 a1 = *(const float4*)(p + 4);
        int r = __brev((unsigned)l) >> 21;
        sm_[0 * 4096 + r] = a0.x;  sm_[0 * 4096 + 2048 + r] = a0.y;
        sm_[1 * 4096 + r] = a0.z;  sm_[1 * 4096 + 2048 + r] = a0.w;
        sm_[2 * 4096 + r] = a1.x;  sm_[2 * 4096 + 2048 + r] = a1.y;
        sm_[3 * 4096 + r] = a1.z;  sm_[3 * 4096 + 2048 + r] = a1.w;
    }
    __syncthreads();
    fft_core4(sm_, false, 512);

    for (int x = threadIdx.x; x <= 1024; x += 512) {
        int m = (2048 - x) & 2047;
        float re8[8], im8[8];
        #pragma unroll
        for (int j = 0; j < 4; j++) {
            float zrk = sm_[j * 4096 + x];
            float zik = sm_[j * 4096 + 2048 + x];
            float zrm = sm_[j * 4096 + m];
            float zim = sm_[j * 4096 + 2048 + m];
            re8[2 * j]     = 0.5f * (zrk + zrm) * ORTHO_SCALE;  // F re
            im8[2 * j]     = 0.5f * (zik - zim) * ORTHO_SCALE;  // F im
            re8[2 * j + 1] = 0.5f * (zik + zim) * ORTHO_SCALE;  // G re
            im8[2 * j + 1] = 0.5f * (zrm - zrk) * ORTHO_SCALE;  // G im
        }
        if (t == 2) {
            float* vt = g_VfT + (size_t)bh * CC_ * KP_ + (size_t)(eg * 16) * KP_ + x;
            #pragma unroll
            for (int j = 0; j < 8; j++) {
                vt[(size_t)(2 * j)     * KP_] = tf32r(re8[j]);
                vt[(size_t)(2 * j + 1) * KP_] = tf32r(im8[j]);
            }
        } else {
            float* dst = ((t == 0) ? g_Qp : g_Kp) + (size_t)bh * XP_ * CC_ + (size_t)x * CC_ + eg * 8;
            float4 lo0, lo1, hi0, hi1;
            lo0.x = tf32r(re8[0]); lo0.y = tf32r(re8[1]); lo0.z = tf32r(re8[2]); lo0.w = tf32r(re8[3]);
            lo1.x = tf32r(re8[4]); lo1.y = tf32r(re8[5]); lo1.z = tf32r(re8[6]); lo1.w = tf32r(re8[7]);
            hi0.x = tf32r(im8[0]); hi0.y = tf32r(im8[1]); hi0.z = tf32r(im8[2]); hi0.w = tf32r(im8[3]);
            hi1.x = tf32r(im8[4]); hi1.y = tf32r(im8[5]); hi1.z = tf32r(im8[6]); hi1.w = tf32r(im8[7]);
            *(float4*)(dst)          = lo0;
            *(float4*)(dst + 4)      = lo1;
            *(float4*)(dst + 64)     = hi0;
            *(float4*)(dst + 64 + 4) = hi1;
        }
    }
}

// ---------------- scores: mma.sync tf32, CTA tile 128x128, K=128 ----------
#define SC_STR  132
#define SC_SMEM (2 * 128 * SC_STR * 4)

__global__ void __launch_bounds__(256) scores_kernel() {
    extern __shared__ float sm[];
    float* As = sm;
    float* Bs = sm + 128 * SC_STR;

    int tid  = threadIdx.x;
    int wid  = tid >> 5;
    int lane = tid & 31;
    int g = lane >> 2;
    int t = lane & 3;
    int wm = wid & 3;
    int wn = wid >> 2;
    int bh = blockIdx.z;
    int x0 = blockIdx.x * 128;
    int y0 = blockIdx.y * 128;

    const float* Qg = g_Qp + (size_t)bh * XP_ * CC_;
    const float* Kg = g_Kp + (size_t)bh * XP_ * CC_;

    for (int idx = tid; idx < 4096; idx += 256) {
        int r  = idx >> 5;
        int f4 = idx & 31;
        *(float4*)&As[r * SC_STR + f4 * 4] = *(const float4*)(Qg + (size_t)(x0 + r) * CC_ + f4 * 4);
        *(float4*)&Bs[r * SC_STR + f4 * 4] = *(const float4*)(Kg + (size_t)(y0 + r) * CC_ + f4 * 4);
    }
    __syncthreads();

    float accr[2][8][4];
    float acci[2][8][4];
    #pragma unroll
    for (int mf = 0; mf < 2; mf++)
        #pragma unroll
        for (int nf = 0; nf < 8; nf++)
            #pragma unroll
            for (int j = 0; j < 4; j++) { accr[mf][nf][j] = 0.f; acci[mf][nf][j] = 0.f; }

    #pragma unroll 1
    for (int kc = 0; kc < 8; kc++) {
        int c0 = kc * 8 + t;
        uint32_t alo[2][4], ahi[2][4], aln[2][4];
        #pragma unroll
        for (int mf = 0; mf < 2; mf++) {
            int r0 = (wm * 32 + mf * 16 + g) * SC_STR;
            int r1 = r0 + 8 * SC_STR;
            alo[mf][0] = __float_as_uint(As[r0 + c0]);
            alo[mf][1] = __float_as_uint(As[r1 + c0]);
            alo[mf][2] = __float_as_uint(As[r0 + c0 + 4]);
            alo[mf][3] = __float_as_uint(As[r1 + c0 + 4]);
            ahi[mf][0] = __float_as_uint(As[r0 + c0 + 64]);
            ahi[mf][1] = __float_as_uint(As[r1 + c0 + 64]);
            ahi[mf][2] = __float_as_uint(As[r0 + c0 + 68]);
            ahi[mf][3] = __float_as_uint(As[r1 + c0 + 68]);
            #pragma unroll
            for (int j = 0; j < 4; j++) aln[mf][j] = alo[mf][j] ^ 0x80000000u;
        }
        #pragma unroll
        for (int nf = 0; nf < 8; nf++) {
            int rB = (wn * 64 + nf * 8 + g) * SC_STR;
            uint32_t blo[2], bhi[2];
            blo[0] = __float_as_uint(Bs[rB + c0]);
            blo[1] = __float_as_uint(Bs[rB + c0 + 4]);
            bhi[0] = __float_as_uint(Bs[rB + c0 + 64]);
            bhi[1] = __float_as_uint(Bs[rB + c0 + 68]);
            #pragma unroll
            for (int mf = 0; mf < 2; mf++) {
                mma8(accr[mf][nf], alo[mf], blo);
                mma8(accr[mf][nf], ahi[mf], bhi);
                mma8(acci[mf][nf], ahi[mf], blo);
                mma8(acci[mf][nf], aln[mf], bhi);
            }
        }
    }

    float* Pg = g_P + (size_t)bh * XP_ * KP_;
    #pragma unroll
    for (int mf = 0; mf < 2; mf++)
        #pragma unroll
        for (int nf = 0; nf < 8; nf++)
            #pragma unroll
            for (int j = 0; j < 4; j++) {
                int x = x0 + wm * 32 + mf * 16 + g + ((j >= 2) ? 8 : 0);
                int y = y0 + wn * 64 + nf * 8 + t * 2 + (j & 1);
                if (x < LF_ && y < LF_) {
                    float re = accr[mf][nf][j];
                    float im = acci[mf][nf][j];
                    Pg[(size_t)x * KP_ + y] = sqrtf(re * re + im * im) * 0.125f;
                }
            }
}

// ---------------- row softmax over y (1025), register-resident ------------
__global__ void __launch_bounds__(256) softmax_kernel() {
    __shared__ float red[8];
    int tid = threadIdx.x;
    float* row = g_P + ((size_t)blockIdx.y * XP_ + blockIdx.x) * KP_;

    float v[5];
    #pragma unroll
    for (int k = 0; k < 4; k++) v[k] = row[tid + 256 * k];
    v[4] = (tid == 0) ? row[1024] : -3.4e38f;

    float m = fmaxf(fmaxf(fmaxf(v[0], v[1]), fmaxf(v[2], v[3])), v[4]);
    #pragma unroll
    for (int o = 16; o > 0; o >>= 1) m = fmaxf(m, __shfl_xor_sync(0xffffffffu, m, o));
    if ((tid & 31) == 0) red[tid >> 5] = m;
    __syncthreads();
    float mx = red[0];
    #pragma unroll
    for (int w = 1; w < 8; w++) mx = fmaxf(mx, red[w]);
    __syncthreads();

    float s = 0.f;
    #pragma unroll
    for (int k = 0; k < 4; k++) { v[k] = __expf(v[k] - mx); s += v[k]; }
    v[4] = (tid == 0) ? __expf(v[4] - mx) : 0.f;
    s += v[4];
    #pragma unroll
    for (int o = 16; o > 0; o >>= 1) s += __shfl_xor_sync(0xffffffffu, s, o);
    if ((tid & 31) == 0) red[tid >> 5] = s;
    __syncthreads();
    float tot = 0.f;
    #pragma unroll
    for (int w = 0; w < 8; w++) tot += red[w];
    float inv = 1.0f / tot;

    #pragma unroll
    for (int k = 0; k < 4; k++) row[tid + 256 * k] = tf32r(v[k] * inv);
    if (tid == 0) row[1024] = tf32r(v[4] * inv);
}

// ---------------- outgemm: D[x][c] = sum_y P[x][y]*VfT[c][y] (mma.sync) ---
#define OG_STR  68
#define OG_SMEM (2 * 128 * OG_STR * 4)

__global__ void __launch_bounds__(256) outgemm_kernel() {
    extern __shared__ float sm[];
    float* As = sm;
    float* Bs = sm + 128 * OG_STR;

    int tid  = threadIdx.x;
    int wid  = tid >> 5;
    int lane = tid & 31;
    int g = lane >> 2;
    int t = lane & 3;
    int wm = wid & 3;
    int wn = wid >> 2;
    int bh = blockIdx.y;
    int x0 = blockIdx.x * 128;

    const float* Pg = g_P   + (size_t)bh * XP_ * KP_;
    const float* Vt = g_VfT + (size_t)bh * CC_ * KP_;

    float acc[2][8][4];
    #pragma unroll
    for (int mf = 0; mf < 2; mf++)
        #pragma unroll
        for (int nf = 0; nf < 8; nf++)
            #pragma unroll
            for (int j = 0; j < 4; j++) acc[mf][nf][j] = 0.f;

    #pragma unroll 1
    for (int ych = 0; ych < 17; ych++) {
        int y0 = ych * 64;
        for (int idx = tid; idx < 2048; idx += 256) {
            int r = idx >> 4, f4 = idx & 15;
            *(float4*)&As[r * OG_STR + f4 * 4] = *(const float4*)(Pg + (size_t)(x0 + r) * KP_ + y0 + f4 * 4);
            *(float4*)&Bs[r * OG_STR + f4 * 4] = *(const float4*)(Vt + (size_t)r * KP_ + y0 + f4 * 4);
        }
        __syncthreads();

        #pragma unroll
        for (int kc = 0; kc < 8; kc++) {
            int c0 = kc * 8 + t;
            uint32_t af[2][4];
            #pragma unroll
            for (int mf = 0; mf < 2; mf++) {
                int r0 = (wm * 32 + mf * 16 + g) * OG_STR;
                int r1 = r0 + 8 * OG_STR;
                af[mf][0] = __float_as_uint(As[r0 + c0]);
                af[mf][1] = __float_as_uint(As[r1 + c0]);
                af[mf][2] = __float_as_uint(As[r0 + c0 + 4]);
                af[mf][3] = __float_as_uint(As[r1 + c0 + 4]);
            }
            #pragma unroll
            for (int nf = 0; nf < 8; nf++) {
                int rB = (wn * 64 + nf * 8 + g) * OG_STR;
                uint32_t bf[2];
                bf[0] = __float_as_uint(Bs[rB + c0]);
                bf[1] = __float_as_uint(Bs[rB + c0 + 4]);
                #pragma unroll
                for (int mf = 0; mf < 2; mf++)
                    mma8(acc[mf][nf], af[mf], bf);
            }
        }
        __syncthreads();
    }

    float* Og = g_Of + (size_t)bh * LF_ * CC_;
    #pragma unroll
    for (int mf = 0; mf < 2; mf++)
        #pragma unroll
        for (int nf = 0; nf < 8; nf++)
            #pragma unroll
            for (int j = 0; j < 4; j++) {
                int x = x0 + wm * 32 + mf * 16 + g + ((j >= 2) ? 8 : 0);
                int c = wn * 64 + nf * 8 + t * 2 + (j & 1);
                if (x < LF_)
                    Og[(size_t)x * CC_ + c] = acc[mf][nf][j];
            }
}

// ---------------- inverse: 8 channels per block via complex packing -------
// grid (BH, 8 e-groups), 512 threads, 64KB dynamic smem.
// Z = S_a + i S_b (both exactly Hermitian; DC/Nyquist imag zeroed) ->
// IFFT(Z) = out_a + i out_b
__global__ void __launch_bounds__(512) fft_inv_kernel(float* __restrict__ out) {
    extern __shared__ float sm_[];
    int bh = blockIdx.x;
    int eg = blockIdx.y;
    int b = bh >> 3;
    int h = bh & 7;

    const float* Obase = g_Of + (size_t)bh * LF_ * CC_ + eg * 16;

    for (int k = threadIdx.x; k < 2048; k += 512) {
        int x = (k <= 1024) ? k : (2048 - k);
        float sg = (k <= 1024) ? 1.f : -1.f;
        bool edge = (k == 0) || (k == 1024);
        const float* row = Obase + (size_t)x * CC_;
        float4 f0 = *(const float4*)(row);
        float4 f1 = *(const float4*)(row + 4);
        float4 f2 = *(const float4*)(row + 8);
        float4 f3 = *(const float4*)(row + 12);
        float vals[16] = {f0.x, f0.y, f0.z, f0.w, f1.x, f1.y, f1.z, f1.w,
                          f2.x, f2.y, f2.z, f2.w, f3.x, f3.y, f3.z, f3.w};
        int r = __brev((unsigned)k) >> 21;
        #pragma unroll
        for (int j = 0; j < 4; j++) {
            float ar = vals[4 * j];
            float ai = edge ? 0.f : sg * vals[4 * j + 1];
            float br = vals[4 * j + 2];
            float bi = edge ? 0.f : sg * vals[4 * j + 3];
            sm_[j * 4096 + r]        = ar - bi;
            sm_[j * 4096 + 2048 + r] = ai + br;
        }
    }
    __syncthreads();
    fft_core4(sm_, true, 512);

    float* obase = out + (size_t)b * L_ * (H_ * E_) + h * E_ + eg * 8;
    for (int l = threadIdx.x; l < 2048; l += 512) {
        float4 o0, o1;
        o0.x = sm_[0 * 4096 + l] * ORTHO_SCALE;
        o0.y = sm_[0 * 4096 + 2048 + l] * ORTHO_SCALE;
        o0.z = sm_[1 * 4096 + l] * ORTHO_SCALE;
        o0.w = sm_[1 * 4096 + 2048 + l] * ORTHO_SCALE;
        o1.x = sm_[2 * 4096 + l] * ORTHO_SCALE;
        o1.y = sm_[2 * 4096 + 2048 + l] * ORTHO_SCALE;
        o1.z = sm_[3 * 4096 + l] * ORTHO_SCALE;
        o1.w = sm_[3 * 4096 + 2048 + l] * ORTHO_SCALE;
        float* p = obase + (size_t)l * (H_ * E_);
        *(float4*)(p)     = o0;
        *(float4*)(p + 4) = o1;
    }
}

// ---------------- launch ----------------
extern "C" void kernel_launch(void* const* d_in, const int* in_sizes, int n_in,
                              void* d_out, int out_size) {
    (void)in_sizes; (void)n_in; (void)out_size;
    const float* q = (const float*)d_in[0];
    const float* k = (const float*)d_in[1];
    const float* v = (const float*)d_in[2];
    float* out = (float*)d_out;

    cudaFuncSetAttribute(scores_kernel,
                         cudaFuncAttributeMaxDynamicSharedMemorySize, SC_SMEM);
    cudaFuncSetAttribute(outgemm_kernel,
                         cudaFuncAttributeMaxDynamicSharedMemorySize, OG_SMEM);
    cudaFuncSetAttribute(fft_fwd_kernel,
                         cudaFuncAttributeMaxDynamicSharedMemorySize, FFT_SMEM);
    cudaFuncSetAttribute(fft_inv_kernel,
                         cudaFuncAttributeMaxDynamicSharedMemorySize, FFT_SMEM);

    init_tw_kernel<<<4, 256>>>();
    fft_fwd_kernel<<<dim3(BH_, 8, 3), 512, FFT_SMEM>>>(q, k, v);
    scores_kernel<<<dim3(9, 9, BH_), 256, SC_SMEM>>>();
    softmax_kernel<<<dim3(LF_, BH_), 256>>>();
    outgemm_kernel<<<dim3(9, BH_), 256, OG_SMEM>>>();
    fft_inv_kernel<<<dim3(BH_, 8), 512, FFT_SMEM>>>(out);
}

// round 10
// speedup vs baseline: 3.4029x; 1.3274x over previous
#include <cuda_runtime.h>
#include <cuda_fp16.h>
#include <math.h>
#include <stdint.h>

// ---------------- problem constants ----------------
#define B_    4
#define H_    8
#define E_    64
#define L_    2048
#define LF_   1025
#define BH_   32
#define CC_   128            // 2*E lanes per frequency bin (lo|hi planar)
#define XP_   1152           // padded rows: 9*128
#define KP_   1088           // padded K for outgemm: 34*32

#define ORTHO_SCALE 0.02209708691207961f   // 1/sqrt(2048)

// ---------------- device scratch (zero-initialized .bss) ----------------
__device__ __half g_Qp [(size_t)BH_ * XP_ * CC_];  // [bh][x][qr(0..63)|qi(64..127)]
__device__ __half g_Kp [(size_t)BH_ * XP_ * CC_];  // [bh][y][kr | ki]
__device__ __half g_VfT[(size_t)BH_ * CC_ * KP_];  // [bh][c][y]
__device__ float  g_P  [(size_t)BH_ * XP_ * KP_];  // raw |scores| (fp32!)
__device__ __half g_Pp [(size_t)BH_ * XP_ * KP_];  // softmax probs (half)
__device__ float  g_Of [(size_t)BH_ * LF_ * CC_];  // mixed complex spectrum (f32)
__device__ float  g_twr[1024];
__device__ float  g_twi[1024];

union H8 { __half h[8]; uint4 u; };

// fp16 warp MMA with fp32 accumulate (sm_80+ baseline; works on compute_103)
static __device__ __forceinline__ void mma16(float* d, const uint32_t* a, const uint32_t* b) {
    asm volatile(
        "mma.sync.aligned.m16n8k16.row.col.f32.f16.f16.f32 "
        "{%0,%1,%2,%3}, {%4,%5,%6,%7}, {%8,%9}, {%0,%1,%2,%3};"
        : "+f"(d[0]), "+f"(d[1]), "+f"(d[2]), "+f"(d[3])
        : "r"(a[0]), "r"(a[1]), "r"(a[2]), "r"(a[3]), "r"(b[0]), "r"(b[1]));
}

// ---------------- twiddle init ----------------
__global__ void init_tw_kernel() {
    int k = blockIdx.x * blockDim.x + threadIdx.x;
    if (k < 1024) {
        float s, c;
        sincospif(-(float)k / 1024.0f, &s, &c);
        g_twr[k] = c;
        g_twi[k] = s;
    }
}

// ------- batched shared-memory radix-2 DIT core: 4 FFTs of N=2048 ---------
__device__ __forceinline__ void fft_core4(float* sm_, bool inverse, int nthr) {
    #pragma unroll 1
    for (int s = 1; s <= 11; s++) {
        int half_  = 1 << (s - 1);
        int shift = 11 - s;
        for (int jj = threadIdx.x; jj < 4096; jj += nthr) {
            int f = jj >> 10;
            int j = jj & 1023;
            float* sr = sm_ + f * 4096;
            float* si = sr + 2048;
            int pos = j & (half_ - 1);
            int i1  = ((j >> (s - 1)) << s) + pos;
            int i2  = i1 + half_;
            int ti  = pos << shift;
            float wr = g_twr[ti];
            float wi = inverse ? -g_twi[ti] : g_twi[ti];
            float xr = sr[i2], xi = si[i2];
            float tr = wr * xr - wi * xi;
            float tq = wr * xi + wi * xr;
            float ar = sr[i1], ai = si[i1];
            sr[i2] = ar - tr;  si[i2] = ai - tq;
            sr[i1] = ar + tr;  si[i1] = ai + tq;
        }
        __syncthreads();
    }
}

// ---------------- forward rfft, 8 channels per block (real-pair packing) ---
#define FFT_SMEM (4 * 4096 * 4)

__global__ void __launch_bounds__(512) fft_fwd_kernel(const float* __restrict__ q,
                                                      const float* __restrict__ k,
                                                      const float* __restrict__ v) {
    extern __shared__ float sm_[];
    int bh = blockIdx.x;
    int eg = blockIdx.y;
    int t  = blockIdx.z;
    int b = bh >> 3;
    int h = bh & 7;
    const float* src = (t == 0) ? q : ((t == 1) ? k : v);
    const float* base = src + (size_t)b * L_ * (H_ * E_) + h * E_ + eg * 8;

    for (int l = threadIdx.x; l < 2048; l += 512) {
        const float* p = base + (size_t)l * (H_ * E_);
        float4 a0 = *(const float4*)(p);
        float4 a1 = *(const float4*)(p + 4);
        int r = __brev((unsigned)l) >> 21;
        sm_[0 * 4096 + r] = a0.x;  sm_[0 * 4096 + 2048 + r] = a0.y;
        sm_[1 * 4096 + r] = a0.z;  sm_[1 * 4096 + 2048 + r] = a0.w;
        sm_[2 * 4096 + r] = a1.x;  sm_[2 * 4096 + 2048 + r] = a1.y;
        sm_[3 * 4096 + r] = a1.z;  sm_[3 * 4096 + 2048 + r] = a1.w;
    }
    __syncthreads();
    fft_core4(sm_, false, 512);

    for (int x = threadIdx.x; x <= 1024; x += 512) {
        int m = (2048 - x) & 2047;
        float re8[8], im8[8];
        #pragma unroll
        for (int j = 0; j < 4; j++) {
            float zrk = sm_[j * 4096 + x];
            float zik = sm_[j * 4096 + 2048 + x];
            float zrm = sm_[j * 4096 + m];
            float zim = sm_[j * 4096 + 2048 + m];
            re8[2 * j]     = 0.5f * (zrk + zrm) * ORTHO_SCALE;  // F re
            im8[2 * j]     = 0.5f * (zik - zim) * ORTHO_SCALE;  // F im
            re8[2 * j + 1] = 0.5f * (zik + zim) * ORTHO_SCALE;  // G re
            im8[2 * j + 1] = 0.5f * (zrm - zrk) * ORTHO_SCALE;  // G im
        }
        if (t == 2) {
            __half* vt = g_VfT + (size_t)bh * CC_ * KP_ + (size_t)(eg * 16) * KP_ + x;
            #pragma unroll
            for (int j = 0; j < 8; j++) {
                vt[(size_t)(2 * j)     * KP_] = __float2half_rn(re8[j]);
                vt[(size_t)(2 * j + 1) * KP_] = __float2half_rn(im8[j]);
            }
        } else {
            __half* dst = ((t == 0) ? g_Qp : g_Kp) + (size_t)bh * XP_ * CC_ + (size_t)x * CC_ + eg * 8;
            H8 lo, hi;
            #pragma unroll
            for (int j = 0; j < 8; j++) {
                lo.h[j] = __float2half_rn(re8[j]);
                hi.h[j] = __float2half_rn(im8[j]);
            }
            *(uint4*)(dst)      = lo.u;
            *(uint4*)(dst + 64) = hi.u;
        }
    }
}

// ---------------- scores: fp16 mma, CTA tile 128x128, complex K=64 ---------
// planar halves in SMEM: As/Bs [128][136] halfs (lo cols 0..63, hi 64..127)
//   re += Alo*Blo + Ahi*Bhi ;  im += Ahi*Blo + (-Alo)*Bhi
#define SC_STRH 136
#define SC_SMEM (2 * 128 * SC_STRH * 2)

__global__ void __launch_bounds__(256) scores_kernel() {
    extern __shared__ __half smh[];
    __half* As = smh;
    __half* Bs = smh + 128 * SC_STRH;

    int tid  = threadIdx.x;
    int wid  = tid >> 5;
    int lane = tid & 31;
    int g = lane >> 2;
    int t = lane & 3;
    int wm = wid & 3;
    int wn = wid >> 2;
    int bh = blockIdx.z;
    int x0 = blockIdx.x * 128;
    int y0 = blockIdx.y * 128;

    const __half* Qg = g_Qp + (size_t)bh * XP_ * CC_;
    const __half* Kg = g_Kp + (size_t)bh * XP_ * CC_;

    for (int idx = tid; idx < 2048; idx += 256) {
        int r = idx >> 4;
        int c = idx & 15;   // 16B chunk (8 halfs)
        *(uint4*)&As[r * SC_STRH + c * 8] = *(const uint4*)(Qg + (size_t)(x0 + r) * CC_ + c * 8);
        *(uint4*)&Bs[r * SC_STRH + c * 8] = *(const uint4*)(Kg + (size_t)(y0 + r) * CC_ + c * 8);
    }
    __syncthreads();

    float accr[2][8][4];
    float acci[2][8][4];
    #pragma unroll
    for (int mf = 0; mf < 2; mf++)
        #pragma unroll
        for (int nf = 0; nf < 8; nf++)
            #pragma unroll
            for (int j = 0; j < 4; j++) { accr[mf][nf][j] = 0.f; acci[mf][nf][j] = 0.f; }

    #pragma unroll 1
    for (int kc = 0; kc < 4; kc++) {
        int c0 = kc * 16 + 2 * t;
        uint32_t alo[2][4], ahi[2][4], aln[2][4];
        #pragma unroll
        for (int mf = 0; mf < 2; mf++) {
            int r0 = (wm * 32 + mf * 16 + g) * SC_STRH;
            int r1 = r0 + 8 * SC_STRH;
            alo[mf][0] = *(const uint32_t*)&As[r0 + c0];
            alo[mf][1] = *(const uint32_t*)&As[r1 + c0];
            alo[mf][2] = *(const uint32_t*)&As[r0 + c0 + 8];
            alo[mf][3] = *(const uint32_t*)&As[r1 + c0 + 8];
            ahi[mf][0] = *(const uint32_t*)&As[r0 + c0 + 64];
            ahi[mf][1] = *(const uint32_t*)&As[r1 + c0 + 64];
            ahi[mf][2] = *(const uint32_t*)&As[r0 + c0 + 72];
            ahi[mf][3] = *(const uint32_t*)&As[r1 + c0 + 72];
            #pragma unroll
            for (int j = 0; j < 4; j++) aln[mf][j] = alo[mf][j] ^ 0x80008000u;
        }
        #pragma unroll
        for (int nf = 0; nf < 8; nf++) {
            int rB = (wn * 64 + nf * 8 + g) * SC_STRH;
            uint32_t blo[2], bhi[2];
            blo[0] = *(const uint32_t*)&Bs[rB + c0];
            blo[1] = *(const uint32_t*)&Bs[rB + c0 + 8];
            bhi[0] = *(const uint32_t*)&Bs[rB + c0 + 64];
            bhi[1] = *(const uint32_t*)&Bs[rB + c0 + 72];
            #pragma unroll
            for (int mf = 0; mf < 2; mf++) {
                mma16(accr[mf][nf], alo[mf], blo);
                mma16(accr[mf][nf], ahi[mf], bhi);
                mma16(acci[mf][nf], ahi[mf], blo);
                mma16(acci[mf][nf], aln[mf], bhi);
            }
        }
    }

    float* Pg = g_P + (size_t)bh * XP_ * KP_;
    #pragma unroll
    for (int mf = 0; mf < 2; mf++)
        #pragma unroll
        for (int nf = 0; nf < 8; nf++) {
            int y = y0 + wn * 64 + nf * 8 + 2 * t;
            if (y >= LF_) continue;
            int xA = x0 + wm * 32 + mf * 16 + g;
            int xB = xA + 8;
            float re, im;
            if (xA < LF_) {
                float2 o;
                re = accr[mf][nf][0]; im = acci[mf][nf][0];
                o.x = sqrtf(re * re + im * im) * 0.125f;
                re = accr[mf][nf][1]; im = acci[mf][nf][1];
                o.y = sqrtf(re * re + im * im) * 0.125f;
                *(float2*)&Pg[(size_t)xA * KP_ + y] = o;
            }
            if (xB < LF_) {
                float2 o;
                re = accr[mf][nf][2]; im = acci[mf][nf][2];
                o.x = sqrtf(re * re + im * im) * 0.125f;
                re = accr[mf][nf][3]; im = acci[mf][nf][3];
                o.y = sqrtf(re * re + im * im) * 0.125f;
                *(float2*)&Pg[(size_t)xB * KP_ + y] = o;
            }
        }
}

// ---------------- row softmax: f32 scores in, half probs out ---------------
__global__ void __launch_bounds__(256) softmax_kernel() {
    __shared__ float red[8];
    int tid = threadIdx.x;
    size_t off = ((size_t)blockIdx.y * XP_ + blockIdx.x) * KP_;
    const float* row = g_P + off;
    __half* prow = g_Pp + off;

    float v[5];
    float4 f = *(const float4*)&row[tid * 4];
    v[0] = f.x; v[1] = f.y; v[2] = f.z; v[3] = f.w;
    v[4] = (tid == 0) ? row[1024] : -3.4e38f;

    float m = fmaxf(fmaxf(fmaxf(v[0], v[1]), fmaxf(v[2], v[3])), v[4]);
    #pragma unroll
    for (int o = 16; o > 0; o >>= 1) m = fmaxf(m, __shfl_xor_sync(0xffffffffu, m, o));
    if ((tid & 31) == 0) red[tid >> 5] = m;
    __syncthreads();
    float mx = red[0];
    #pragma unroll
    for (int w = 1; w < 8; w++) mx = fmaxf(mx, red[w]);
    __syncthreads();

    float s = 0.f;
    #pragma unroll
    for (int k = 0; k < 4; k++) { v[k] = __expf(v[k] - mx); s += v[k]; }
    v[4] = (tid == 0) ? __expf(v[4] - mx) : 0.f;
    s += v[4];
    #pragma unroll
    for (int o = 16; o > 0; o >>= 1) s += __shfl_xor_sync(0xffffffffu, s, o);
    if ((tid & 31) == 0) red[tid >> 5] = s;
    __syncthreads();
    float tot = 0.f;
    #pragma unroll
    for (int w = 0; w < 8; w++) tot += red[w];
    float inv = 1.0f / tot;

    H8 pk;
    pk.h[0] = __float2half_rn(v[0] * inv);
    pk.h[1] = __float2half_rn(v[1] * inv);
    pk.h[2] = __float2half_rn(v[2] * inv);
    pk.h[3] = __float2half_rn(v[3] * inv);
    *(uint2*)&prow[tid * 4] = make_uint2(pk.u.x, pk.u.y);
    if (tid == 0) prow[1024] = __float2half_rn(v[4] * inv);
}

// ---------------- outgemm: D[x][c] = sum_y Pp[x][y]*VfT[c][y] (fp16 mma) ---
#define OG_STRH 72
#define OG_SMEM (2 * 128 * OG_STRH * 2)

__global__ void __launch_bounds__(256) outgemm_kernel() {
    extern __shared__ __half smh[];
    __half* As = smh;
    __half* Bs = smh + 128 * OG_STRH;

    int tid  = threadIdx.x;
    int wid  = tid >> 5;
    int lane = tid & 31;
    int g = lane >> 2;
    int t = lane & 3;
    int wm = wid & 3;
    int wn = wid >> 2;
    int bh = blockIdx.y;
    int x0 = blockIdx.x * 128;

    const __half* Pg = g_Pp  + (size_t)bh * XP_ * KP_;
    const __half* Vt = g_VfT + (size_t)bh * CC_ * KP_;

    float acc[2][8][4];
    #pragma unroll
    for (int mf = 0; mf < 2; mf++)
        #pragma unroll
        for (int nf = 0; nf < 8; nf++)
            #pragma unroll
            for (int j = 0; j < 4; j++) acc[mf][nf][j] = 0.f;

    #pragma unroll 1
    for (int ych = 0; ych < 17; ych++) {
        int y0 = ych * 64;
        for (int idx = tid; idx < 1024; idx += 256) {
            int r = idx >> 3, c = idx & 7;
            *(uint4*)&As[r * OG_STRH + c * 8] = *(const uint4*)(Pg + (size_t)(x0 + r) * KP_ + y0 + c * 8);
            *(uint4*)&Bs[r * OG_STRH + c * 8] = *(const uint4*)(Vt + (size_t)r * KP_ + y0 + c * 8);
        }
        __syncthreads();

        #pragma unroll
        for (int kc = 0; kc < 4; kc++) {
            int c0 = kc * 16 + 2 * t;
            uint32_t af[2][4];
            #pragma unroll
            for (int mf = 0; mf < 2; mf++) {
                int r0 = (wm * 32 + mf * 16 + g) * OG_STRH;
                int r1 = r0 + 8 * OG_STRH;
                af[mf][0] = *(const uint32_t*)&As[r0 + c0];
                af[mf][1] = *(const uint32_t*)&As[r1 + c0];
                af[mf][2] = *(const uint32_t*)&As[r0 + c0 + 8];
                af[mf][3] = *(const uint32_t*)&As[r1 + c0 + 8];
            }
            #pragma unroll
            for (int nf = 0; nf < 8; nf++) {
                int rB = (wn * 64 + nf * 8 + g) * OG_STRH;
                uint32_t bf[2];
                bf[0] = *(const uint32_t*)&Bs[rB + c0];
                bf[1] = *(const uint32_t*)&Bs[rB + c0 + 8];
                #pragma unroll
                for (int mf = 0; mf < 2; mf++)
                    mma16(acc[mf][nf], af[mf], bf);
            }
        }
        __syncthreads();
    }

    float* Og = g_Of + (size_t)bh * LF_ * CC_;
    #pragma unroll
    for (int mf = 0; mf < 2; mf++)
        #pragma unroll
        for (int nf = 0; nf < 8; nf++) {
            int c = wn * 64 + nf * 8 + 2 * t;
            int xA = x0 + wm * 32 + mf * 16 + g;
            int xB = xA + 8;
            if (xA < LF_) {
                float2 o; o.x = acc[mf][nf][0]; o.y = acc[mf][nf][1];
                *(float2*)&Og[(size_t)xA * CC_ + c] = o;
            }
            if (xB < LF_) {
                float2 o; o.x = acc[mf][nf][2]; o.y = acc[mf][nf][3];
                *(float2*)&Og[(size_t)xB * CC_ + c] = o;
            }
        }
}

// ---------------- inverse: 8 channels per block via complex packing -------
__global__ void __launch_bounds__(512) fft_inv_kernel(float* __restrict__ out) {
    extern __shared__ float sm_[];
    int bh = blockIdx.x;
    int eg = blockIdx.y;
    int b = bh >> 3;
    int h = bh & 7;

    const float* Obase = g_Of + (size_t)bh * LF_ * CC_ + eg * 16;

    for (int k = threadIdx.x; k < 2048; k += 512) {
        int x = (k <= 1024) ? k : (2048 - k);
        float sg = (k <= 1024) ? 1.f : -1.f;
        bool edge = (k == 0) || (k == 1024);
        const float* row = Obase + (size_t)x * CC_;
        float4 f0 = *(const float4*)(row);
        float4 f1 = *(const float4*)(row + 4);
        float4 f2 = *(const float4*)(row + 8);
        float4 f3 = *(const float4*)(row + 12);
        float vals[16] = {f0.x, f0.y, f0.z, f0.w, f1.x, f1.y, f1.z, f1.w,
                          f2.x, f2.y, f2.z, f2.w, f3.x, f3.y, f3.z, f3.w};
        int r = __brev((unsigned)k) >> 21;
        #pragma unroll
        for (int j = 0; j < 4; j++) {
            float ar = vals[4 * j];
            float ai = edge ? 0.f : sg * vals[4 * j + 1];
            float br = vals[4 * j + 2];
            float bi = edge ? 0.f : sg * vals[4 * j + 3];
            sm_[j * 4096 + r]        = ar - bi;
            sm_[j * 4096 + 2048 + r] = ai + br;
        }
    }
    __syncthreads();
    fft_core4(sm_, true, 512);

    float* obase = out + (size_t)b * L_ * (H_ * E_) + h * E_ + eg * 8;
    for (int l = threadIdx.x; l < 2048; l += 512) {
        float4 o0, o1;
        o0.x = sm_[0 * 4096 + l] * ORTHO_SCALE;
        o0.y = sm_[0 * 4096 + 2048 + l] * ORTHO_SCALE;
        o0.z = sm_[1 * 4096 + l] * ORTHO_SCALE;
        o0.w = sm_[1 * 4096 + 2048 + l] * ORTHO_SCALE;
        o1.x = sm_[2 * 4096 + l] * ORTHO_SCALE;
        o1.y = sm_[2 * 4096 + 2048 + l] * ORTHO_SCALE;
        o1.z = sm_[3 * 4096 + l] * ORTHO_SCALE;
        o1.w = sm_[3 * 4096 + 2048 + l] * ORTHO_SCALE;
        float* p = obase + (size_t)l * (H_ * E_);
        *(float4*)(p)     = o0;
        *(float4*)(p + 4) = o1;
    }
}

// ---------------- launch ----------------
extern "C" void kernel_launch(void* const* d_in, const int* in_sizes, int n_in,
                              void* d_out, int out_size) {
    (void)in_sizes; (void)n_in; (void)out_size;
    const float* q = (const float*)d_in[0];
    const float* k = (const float*)d_in[1];
    const float* v = (const float*)d_in[2];
    float* out = (float*)d_out;

    cudaFuncSetAttribute(scores_kernel,
                         cudaFuncAttributeMaxDynamicSharedMemorySize, SC_SMEM);
    cudaFuncSetAttribute(outgemm_kernel,
                         cudaFuncAttributeMaxDynamicSharedMemorySize, OG_SMEM);
    cudaFuncSetAttribute(fft_fwd_kernel,
                         cudaFuncAttributeMaxDynamicSharedMemorySize, FFT_SMEM);
    cudaFuncSetAttribute(fft_inv_kernel,
                         cudaFuncAttributeMaxDynamicSharedMemorySize, FFT_SMEM);

    init_tw_kernel<<<4, 256>>>();
    fft_fwd_kernel<<<dim3(BH_, 8, 3), 512, FFT_SMEM>>>(q, k, v);
    scores_kernel<<<dim3(9, 9, BH_), 256, SC_SMEM>>>();
    softmax_kernel<<<dim3(LF_, BH_), 256>>>();
    outgemm_kernel<<<dim3(9, BH_), 256, OG_SMEM>>>();
    fft_inv_kernel<<<dim3(BH_, 8), 512, FFT_SMEM>>>(out);
}

// round 15
// speedup vs baseline: 4.5538x; 1.3382x over previous
#include <cuda_runtime.h>
#include <cuda_fp16.h>
#include <math.h>
#include <stdint.h>

// ---------------- problem constants ----------------
#define B_    4
#define H_    8
#define E_    64
#define L_    2048
#define LF_   1025
#define BH_   32
#define CC_   128            // 2*E lanes per frequency bin (lo|hi planar)
#define XP_   1152           // padded rows: 9*128
#define KP_   1088           // padded K for V^T layout: 34*32

#define ORTHO_SCALE 0.02209708691207961f   // 1/sqrt(2048)

// ---------------- device scratch (zero-initialized .bss) ----------------
__device__ __half g_Qp [(size_t)BH_ * XP_ * CC_];  // [bh][x][qr(0..63)|qi(64..127)]
__device__ __half g_Kp [(size_t)BH_ * XP_ * CC_];  // [bh][y][kr | ki]
__device__ __half g_VfT[(size_t)BH_ * CC_ * KP_];  // [bh][c][y]
__device__ float  g_Of [(size_t)BH_ * LF_ * CC_];  // mixed complex spectrum (f32)
__device__ float  g_twr[1024];
__device__ float  g_twi[1024];

union H8 { __half h[8]; uint4 u; };

// fp16 warp MMA with fp32 accumulate (sm_80+ baseline; works on compute_103)
static __device__ __forceinline__ void mma16(float* d, const uint32_t* a, const uint32_t* b) {
    asm volatile(
        "mma.sync.aligned.m16n8k16.row.col.f32.f16.f16.f32 "
        "{%0,%1,%2,%3}, {%4,%5,%6,%7}, {%8,%9}, {%0,%1,%2,%3};"
        : "+f"(d[0]), "+f"(d[1]), "+f"(d[2]), "+f"(d[3])
        : "r"(a[0]), "r"(a[1]), "r"(a[2]), "r"(a[3]), "r"(b[0]), "r"(b[1]));
}

// ---------------- twiddle init ----------------
__global__ void init_tw_kernel() {
    int k = blockIdx.x * blockDim.x + threadIdx.x;
    if (k < 1024) {
        float s, c;
        sincospif(-(float)k / 1024.0f, &s, &c);
        g_twr[k] = c;
        g_twi[k] = s;
    }
}

// ------- batched shared-memory radix-2 DIT core: 4 FFTs of N=2048 ---------
__device__ __forceinline__ void fft_core4(float* sm_, bool inverse, int nthr) {
    #pragma unroll 1
    for (int s = 1; s <= 11; s++) {
        int half_  = 1 << (s - 1);
        int shift = 11 - s;
        for (int jj = threadIdx.x; jj < 4096; jj += nthr) {
            int f = jj >> 10;
            int j = jj & 1023;
            float* sr = sm_ + f * 4096;
            float* si = sr + 2048;
            int pos = j & (half_ - 1);
            int i1  = ((j >> (s - 1)) << s) + pos;
            int i2  = i1 + half_;
            int ti  = pos << shift;
            float wr = g_twr[ti];
            float wi = inverse ? -g_twi[ti] : g_twi[ti];
            float xr = sr[i2], xi = si[i2];
            float tr = wr * xr - wi * xi;
            float tq = wr * xi + wi * xr;
            float ar = sr[i1], ai = si[i1];
            sr[i2] = ar - tr;  si[i2] = ai - tq;
            sr[i1] = ar + tr;  si[i1] = ai + tq;
        }
        __syncthreads();
    }
}

// ---------------- forward rfft, 8 channels per block (real-pair packing) ---
#define FFT_SMEM (4 * 4096 * 4)

__global__ void __launch_bounds__(512) fft_fwd_kernel(const float* __restrict__ q,
                                                      const float* __restrict__ k,
                                                      const float* __restrict__ v) {
    extern __shared__ float sm_[];
    int bh = blockIdx.x;
    int eg = blockIdx.y;
    int t  = blockIdx.z;
    int b = bh >> 3;
    int h = bh & 7;
    const float* src = (t == 0) ? q : ((t == 1) ? k : v);
    const float* base = src + (size_t)b * L_ * (H_ * E_) + h * E_ + eg * 8;

    for (int l = threadIdx.x; l < 2048; l += 512) {
        const float* p = base + (size_t)l * (H_ * E_);
        float4 a0 = *(const float4*)(p);
        float4 a1 = *(const float4*)(p + 4);
        int r = __brev((unsigned)l) >> 21;
        sm_[0 * 4096 + r] = a0.x;  sm_[0 * 4096 + 2048 + r] = a0.y;
        sm_[1 * 4096 + r] = a0.z;  sm_[1 * 4096 + 2048 + r] = a0.w;
        sm_[2 * 4096 + r] = a1.x;  sm_[2 * 4096 + 2048 + r] = a1.y;
        sm_[3 * 4096 + r] = a1.z;  sm_[3 * 4096 + 2048 + r] = a1.w;
    }
    __syncthreads();
    fft_core4(sm_, false, 512);

    for (int x = threadIdx.x; x <= 1024; x += 512) {
        int m = (2048 - x) & 2047;
        float re8[8], im8[8];
        #pragma unroll
        for (int j = 0; j < 4; j++) {
            float zrk = sm_[j * 4096 + x];
            float zik = sm_[j * 4096 + 2048 + x];
            float zrm = sm_[j * 4096 + m];
            float zim = sm_[j * 4096 + 2048 + m];
            re8[2 * j]     = 0.5f * (zrk + zrm) * ORTHO_SCALE;  // F re
            im8[2 * j]     = 0.5f * (zik - zim) * ORTHO_SCALE;  // F im
            re8[2 * j + 1] = 0.5f * (zik + zim) * ORTHO_SCALE;  // G re
            im8[2 * j + 1] = 0.5f * (zrm - zrk) * ORTHO_SCALE;  // G im
        }
        if (t == 2) {
            __half* vt = g_VfT + (size_t)bh * CC_ * KP_ + (size_t)(eg * 16) * KP_ + x;
            #pragma unroll
            for (int j = 0; j < 8; j++) {
                vt[(size_t)(2 * j)     * KP_] = __float2half_rn(re8[j]);
                vt[(size_t)(2 * j + 1) * KP_] = __float2half_rn(im8[j]);
            }
        } else {
            __half* dst = ((t == 0) ? g_Qp : g_Kp) + (size_t)bh * XP_ * CC_ + (size_t)x * CC_ + eg * 8;
            H8 lo, hi;
            #pragma unroll
            for (int j = 0; j < 8; j++) {
                lo.h[j] = __float2half_rn(re8[j]);
                hi.h[j] = __float2half_rn(im8[j]);
            }
            *(uint4*)(dst)      = lo.u;
            *(uint4*)(dst + 64) = hi.u;
        }
    }
}

// ============== fused scores + online-softmax + PV (flash-style) ==========
// grid (9 x-blocks, BH), 256 threads (8 warps). Warp wid owns x-rows
// [x0+wid*16, x0+wid*16+16) and ALL 128 output channels (O[16][4]).
// y processed in 17 K/V tiles of 64, each as two 32-wide sub-tiles.
// SMEM: Qs[128][136]h, Ks[64][136]h, Vs[128][72]h  = 70656 B
#define FA_QS  0
#define FA_KS  (128 * 136)
#define FA_VS  (128 * 136 + 64 * 136)
#define FA_SMEM ((128 * 136 + 64 * 136 + 128 * 72) * 2)

__global__ void __launch_bounds__(256) fused_attn_kernel() {
    extern __shared__ __half smh[];
    __half* Qs = smh + FA_QS;
    __half* Ks = smh + FA_KS;
    __half* Vs = smh + FA_VS;

    int tid  = threadIdx.x;
    int wid  = tid >> 5;
    int lane = tid & 31;
    int g = lane >> 2;
    int t = lane & 3;
    int bh = blockIdx.y;
    int x0 = blockIdx.x * 128;

    const __half* Qg = g_Qp + (size_t)bh * XP_ * CC_;
    const __half* Kg = g_Kp + (size_t)bh * XP_ * CC_;
    const __half* Vt = g_VfT + (size_t)bh * CC_ * KP_;

    // load Q tile once
    for (int idx = tid; idx < 2048; idx += 256) {
        int r = idx >> 4, c = idx & 15;
        *(uint4*)&Qs[r * 136 + c * 8] = *(const uint4*)(Qg + (size_t)(x0 + r) * CC_ + c * 8);
    }

    float O[16][4];
    #pragma unroll
    for (int i = 0; i < 16; i++)
        #pragma unroll
        for (int j = 0; j < 4; j++) O[i][j] = 0.f;
    float m0 = -1e30f, m1 = -1e30f, l0 = 0.f, l1 = 0.f;

    int r0q = (wid * 16 + g) * 136;
    int r1q = r0q + 8 * 136;

    #pragma unroll 1
    for (int yt = 0; yt < 17; yt++) {
        int y0 = yt * 64;
        __syncthreads();
        for (int idx = tid; idx < 1024; idx += 256) {
            int r = idx >> 4, c = idx & 15;
            *(uint4*)&Ks[r * 136 + c * 8] = *(const uint4*)(Kg + (size_t)(y0 + r) * CC_ + c * 8);
        }
        for (int idx = tid; idx < 1024; idx += 256) {
            int r = idx >> 3, c = idx & 7;
            *(uint4*)&Vs[r * 72 + c * 8] = *(const uint4*)(Vt + (size_t)r * KP_ + y0 + c * 8);
        }
        __syncthreads();

        #pragma unroll 1
        for (int hf = 0; hf < 2; hf++) {
            int ysub = y0 + 32 * hf;

            // ---- scores sub-tile: S[16][32] complex, K=64 (planar halves) --
            float sre[4][4], sim[4][4];
            #pragma unroll
            for (int nf = 0; nf < 4; nf++)
                #pragma unroll
                for (int j = 0; j < 4; j++) { sre[nf][j] = 0.f; sim[nf][j] = 0.f; }

            #pragma unroll
            for (int kc = 0; kc < 4; kc++) {
                int c0 = kc * 16 + 2 * t;
                uint32_t alo[4], ahi[4], aln[4];
                alo[0] = *(const uint32_t*)&Qs[r0q + c0];
                alo[1] = *(const uint32_t*)&Qs[r1q + c0];
                alo[2] = *(const uint32_t*)&Qs[r0q + c0 + 8];
                alo[3] = *(const uint32_t*)&Qs[r1q + c0 + 8];
                ahi[0] = *(const uint32_t*)&Qs[r0q + c0 + 64];
                ahi[1] = *(const uint32_t*)&Qs[r1q + c0 + 64];
                ahi[2] = *(const uint32_t*)&Qs[r0q + c0 + 72];
                ahi[3] = *(const uint32_t*)&Qs[r1q + c0 + 72];
                #pragma unroll
                for (int j = 0; j < 4; j++) aln[j] = alo[j] ^ 0x80008000u;
                #pragma unroll
                for (int nf = 0; nf < 4; nf++) {
                    int rB = (32 * hf + nf * 8 + g) * 136;
                    uint32_t blo[2], bhi[2];
                    blo[0] = *(const uint32_t*)&Ks[rB + c0];
                    blo[1] = *(const uint32_t*)&Ks[rB + c0 + 8];
                    bhi[0] = *(const uint32_t*)&Ks[rB + c0 + 64];
                    bhi[1] = *(const uint32_t*)&Ks[rB + c0 + 72];
                    mma16(sre[nf], alo, blo);
                    mma16(sre[nf], ahi, bhi);
                    mma16(sim[nf], ahi, blo);
                    mma16(sim[nf], aln, bhi);
                }
            }

            // ---- |s|/8 with y-padding mask ----
            bool tail = (ysub + 32 > LF_);
            float tmax0 = -1e30f, tmax1 = -1e30f;
            #pragma unroll
            for (int nf = 0; nf < 4; nf++)
                #pragma unroll
                for (int j = 0; j < 4; j++) {
                    float re = sre[nf][j], im = sim[nf][j];
                    float s = sqrtf(re * re + im * im) * 0.125f;
                    if (tail) {
                        int y = ysub + nf * 8 + 2 * t + (j & 1);
                        if (y >= LF_) s = -1e30f;
                    }
                    sre[nf][j] = s;
                    if (j < 2) tmax0 = fmaxf(tmax0, s);
                    else       tmax1 = fmaxf(tmax1, s);
                }
            tmax0 = fmaxf(tmax0, __shfl_xor_sync(0xffffffffu, tmax0, 1));
            tmax0 = fmaxf(tmax0, __shfl_xor_sync(0xffffffffu, tmax0, 2));
            tmax1 = fmaxf(tmax1, __shfl_xor_sync(0xffffffffu, tmax1, 1));
            tmax1 = fmaxf(tmax1, __shfl_xor_sync(0xffffffffu, tmax1, 2));

            float mn0 = fmaxf(m0, tmax0);
            float mn1 = fmaxf(m1, tmax1);
            float cf0 = __expf(m0 - mn0);
            float cf1 = __expf(m1 - mn1);
            m0 = mn0; m1 = mn1;
            l0 *= cf0; l1 *= cf1;
            #pragma unroll
            for (int cnf = 0; cnf < 16; cnf++) {
                O[cnf][0] *= cf0; O[cnf][1] *= cf0;
                O[cnf][2] *= cf1; O[cnf][3] *= cf1;
            }

            // ---- p = exp(s-m), pack to fp16 A-fragments ----
            float sum0 = 0.f, sum1 = 0.f;
            uint32_t ph[4][2];
            #pragma unroll
            for (int nf = 0; nf < 4; nf++) {
                float p0 = __expf(sre[nf][0] - m0);
                float p1 = __expf(sre[nf][1] - m0);
                float p2 = __expf(sre[nf][2] - m1);
                float p3 = __expf(sre[nf][3] - m1);
                sum0 += p0 + p1;
                sum1 += p2 + p3;
                __half2 h01 = __floats2half2_rn(p0, p1);
                __half2 h23 = __floats2half2_rn(p2, p3);
                ph[nf][0] = *(uint32_t*)&h01;
                ph[nf][1] = *(uint32_t*)&h23;
            }
            sum0 += __shfl_xor_sync(0xffffffffu, sum0, 1);
            sum0 += __shfl_xor_sync(0xffffffffu, sum0, 2);
            sum1 += __shfl_xor_sync(0xffffffffu, sum1, 1);
            sum1 += __shfl_xor_sync(0xffffffffu, sum1, 2);
            l0 += sum0; l1 += sum1;

            // ---- PV: O[16 rows][128 c] += P[16][32y] * V[y][c] ----
            #pragma unroll
            for (int kc = 0; kc < 2; kc++) {
                uint32_t aP[4] = { ph[2 * kc][0], ph[2 * kc][1],
                                   ph[2 * kc + 1][0], ph[2 * kc + 1][1] };
                int kcol = 32 * hf + kc * 16 + 2 * t;
                #pragma unroll
                for (int cnf = 0; cnf < 16; cnf++) {
                    int rV = (cnf * 8 + g) * 72;
                    uint32_t bf[2];
                    bf[0] = *(const uint32_t*)&Vs[rV + kcol];
                    bf[1] = *(const uint32_t*)&Vs[rV + kcol + 8];
                    mma16(O[cnf], aP, bf);
                }
            }
        }
    }

    // ---- epilogue: normalize, write Of ----
    float i0 = 1.f / l0;
    float i1 = 1.f / l1;
    int xa = x0 + wid * 16 + g;
    int xb = xa + 8;
    float* Og = g_Of + (size_t)bh * LF_ * CC_;
    #pragma unroll
    for (int cnf = 0; cnf < 16; cnf++) {
        int c = cnf * 8 + 2 * t;
        if (xa < LF_) {
            float2 o; o.x = O[cnf][0] * i0; o.y = O[cnf][1] * i0;
            *(float2*)&Og[(size_t)xa * CC_ + c] = o;
        }
        if (xb < LF_) {
            float2 o; o.x = O[cnf][2] * i1; o.y = O[cnf][3] * i1;
            *(float2*)&Og[(size_t)xb * CC_ + c] = o;
        }
    }
}

// ---------------- inverse: 8 channels per block via complex packing -------
__global__ void __launch_bounds__(512) fft_inv_kernel(float* __restrict__ out) {
    extern __shared__ float sm_[];
    int bh = blockIdx.x;
    int eg = blockIdx.y;
    int b = bh >> 3;
    int h = bh & 7;

    const float* Obase = g_Of + (size_t)bh * LF_ * CC_ + eg * 16;

    for (int k = threadIdx.x; k < 2048; k += 512) {
        int x = (k <= 1024) ? k : (2048 - k);
        float sg = (k <= 1024) ? 1.f : -1.f;
        bool edge = (k == 0) || (k == 1024);
        const float* row = Obase + (size_t)x * CC_;
        float4 f0 = *(const float4*)(row);
        float4 f1 = *(const float4*)(row + 4);
        float4 f2 = *(const float4*)(row + 8);
        float4 f3 = *(const float4*)(row + 12);
        float vals[16] = {f0.x, f0.y, f0.z, f0.w, f1.x, f1.y, f1.z, f1.w,
                          f2.x, f2.y, f2.z, f2.w, f3.x, f3.y, f3.z, f3.w};
        int r = __brev((unsigned)k) >> 21;
        #pragma unroll
        for (int j = 0; j < 4; j++) {
            float ar = vals[4 * j];
            float ai = edge ? 0.f : sg * vals[4 * j + 1];
            float br = vals[4 * j + 2];
            float bi = edge ? 0.f : sg * vals[4 * j + 3];
            sm_[j * 4096 + r]        = ar - bi;
            sm_[j * 4096 + 2048 + r] = ai + br;
        }
    }
    __syncthreads();
    fft_core4(sm_, true, 512);

    float* obase = out + (size_t)b * L_ * (H_ * E_) + h * E_ + eg * 8;
    for (int l = threadIdx.x; l < 2048; l += 512) {
        float4 o0, o1;
        o0.x = sm_[0 * 4096 + l] * ORTHO_SCALE;
        o0.y = sm_[0 * 4096 + 2048 + l] * ORTHO_SCALE;
        o0.z = sm_[1 * 4096 + l] * ORTHO_SCALE;
        o0.w = sm_[1 * 4096 + 2048 + l] * ORTHO_SCALE;
        o1.x = sm_[2 * 4096 + l] * ORTHO_SCALE;
        o1.y = sm_[2 * 4096 + 2048 + l] * ORTHO_SCALE;
        o1.z = sm_[3 * 4096 + l] * ORTHO_SCALE;
        o1.w = sm_[3 * 4096 + 2048 + l] * ORTHO_SCALE;
        float* p = obase + (size_t)l * (H_ * E_);
        *(float4*)(p)     = o0;
        *(float4*)(p + 4) = o1;
    }
}

// ---------------- launch ----------------
extern "C" void kernel_launch(void* const* d_in, const int* in_sizes, int n_in,
                              void* d_out, int out_size) {
    (void)in_sizes; (void)n_in; (void)out_size;
    const float* q = (const float*)d_in[0];
    const float* k = (const float*)d_in[1];
    const float* v = (const float*)d_in[2];
    float* out = (float*)d_out;

    cudaFuncSetAttribute(fused_attn_kernel,
                         cudaFuncAttributeMaxDynamicSharedMemorySize, FA_SMEM);
    cudaFuncSetAttribute(fft_fwd_kernel,
                         cudaFuncAttributeMaxDynamicSharedMemorySize, FFT_SMEM);
    cudaFuncSetAttribute(fft_inv_kernel,
                         cudaFuncAttributeMaxDynamicSharedMemorySize, FFT_SMEM);

    init_tw_kernel<<<4, 256>>>();
    fft_fwd_kernel<<<dim3(BH_, 8, 3), 512, FFT_SMEM>>>(q, k, v);
    fused_attn_kernel<<<dim3(9, BH_), 256, FA_SMEM>>>();
    fft_inv_kernel<<<dim3(BH_, 8), 512, FFT_SMEM>>>(out);
}